// round 6
// baseline (speedup 1.0000x reference)
#include <cuda_runtime.h>
#include <cstdint>

#define Bb   2
#define Nn   2048
#define Cc   512
#define Hh   8
#define HD   64
#define BH   16
#define KTOP 1024
#define SCALEF 0.125f

typedef unsigned long long ull;

// ---------------- scratch ----------------
__device__ uint2 g_Qhl[BH * Nn * HD];                // packed (tf32 hi, tf32 lo)
__device__ uint2 g_Khl[BH * Nn * HD];
__device__ float g_Vh[BH * Nn * HD];
__device__ float g_attn[(size_t)BH * Nn * Nn];
__device__ float g_attnT[(size_t)BH * Nn * Nn];
__device__ float g_rth[BH * Nn];
__device__ float g_cth[BH * Nn];
__device__ float g_rmax[BH * Nn];
__device__ float g_O[BH * Nn * HD];

// ---------------- helpers ----------------
__device__ __forceinline__ unsigned tf32_rna(float x) {
    unsigned u; asm("cvt.rna.tf32.f32 %0, %1;" : "=r"(u) : "f"(x)); return u;
}
__device__ __forceinline__ uint2 split_tf32(float x) {
    unsigned hi = tf32_rna(x);
    unsigned lo = tf32_rna(x - __uint_as_float(hi));
    return make_uint2(hi, lo);
}
__device__ __forceinline__ void mma_tf32(float* c, const unsigned* a, const unsigned* b) {
    asm("mma.sync.aligned.m16n8k8.row.col.f32.tf32.tf32.f32 "
        "{%0,%1,%2,%3},{%4,%5,%6,%7},{%8,%9},{%0,%1,%2,%3};"
        : "+f"(c[0]), "+f"(c[1]), "+f"(c[2]), "+f"(c[3])
        : "r"(a[0]), "r"(a[1]), "r"(a[2]), "r"(a[3]), "r"(b[0]), "r"(b[1]));
}
__device__ __forceinline__ ull pack2(float lo, float hi) {
    ull r; asm("mov.b64 %0,{%1,%2};" : "=l"(r) : "f"(lo), "f"(hi)); return r;
}
__device__ __forceinline__ void ffma2(ull& d, ull a, ull b) {
    asm("fma.rn.f32x2 %0,%1,%2,%3;" : "=l"(d) : "l"(a), "l"(b), "l"(d));
}
__device__ __forceinline__ float2 unpack2(ull v) {
    float2 f; asm("mov.b64 {%0,%1},%2;" : "=f"(f.x), "=f"(f.y) : "l"(v)); return f;
}

// ---------------------------------------------------------------------------
// Kernel 1: projections  out = X @ W^T.  which: 0=Q(hi/lo) 1=K(hi/lo) 2=V(f32)
// tile 128x64, 128 threads, 8x8 per thread (R2 proven core)
// ---------------------------------------------------------------------------
__global__ __launch_bounds__(128) void proj_kernel(const float* __restrict__ X,
                                                   const float* __restrict__ W,
                                                   int which) {
    __shared__ float As[128][33];
    __shared__ float Bs[64][33];
    int tid = threadIdx.x;
    int tx = tid & 7, ty = tid >> 3;
    int m0 = blockIdx.y * 128, n0 = blockIdx.x * 64;
    float acc[8][8] = {};
    for (int k0 = 0; k0 < Cc; k0 += 32) {
#pragma unroll
        for (int l = tid; l < 1024; l += 128) {
            int m = l >> 3, c = (l & 7) * 4;
            float4 v = *(const float4*)&X[(size_t)(m0 + m) * Cc + k0 + c];
            As[m][c] = v.x; As[m][c + 1] = v.y; As[m][c + 2] = v.z; As[m][c + 3] = v.w;
        }
#pragma unroll
        for (int l = tid; l < 512; l += 128) {
            int n = l >> 3, c = (l & 7) * 4;
            float4 v = *(const float4*)&W[(size_t)(n0 + n) * Cc + k0 + c];
            Bs[n][c] = v.x; Bs[n][c + 1] = v.y; Bs[n][c + 2] = v.z; Bs[n][c + 3] = v.w;
        }
        __syncthreads();
#pragma unroll
        for (int kk = 0; kk < 32; kk++) {
            float a[8], b[8];
#pragma unroll
            for (int i = 0; i < 8; i++) a[i] = As[8 * ty + i][kk];
#pragma unroll
            for (int j = 0; j < 8; j++) b[j] = Bs[8 * tx + j][kk];
#pragma unroll
            for (int i = 0; i < 8; i++)
#pragma unroll
                for (int j = 0; j < 8; j++) acc[i][j] += a[i] * b[j];
        }
        __syncthreads();
    }
#pragma unroll
    for (int i = 0; i < 8; i++) {
        int m = m0 + 8 * ty + i;
        int bb = m >> 11, nl = m & (Nn - 1);
#pragma unroll
        for (int j = 0; j < 8; j++) {
            int n = n0 + 8 * tx + j;
            int h = n >> 6, d = n & 63;
            size_t idx = (((size_t)(bb * Hh + h)) * Nn + nl) * HD + d;
            if (which == 2)       g_Vh[idx]  = acc[i][j];
            else if (which == 0)  g_Qhl[idx] = split_tf32(acc[i][j]);
            else                  g_Khl[idx] = split_tf32(acc[i][j]);
        }
    }
}

// ---------------------------------------------------------------------------
// Kernel 2: attn = scale * Q K^T via 3xTF32 mma.sync on PRE-SPLIT operands.
// Block 256, tile M=128 x N=32, K chunks of 32.
// Ts overlay stride 36 (144B = 9x16 -> float4-aligned rows; R4-proven).
// ---------------------------------------------------------------------------
__global__ __launch_bounds__(256) void qk_tc_kernel() {
    __shared__ __align__(16) uint2 Qs2[128][33];
    __shared__ __align__(16) uint2 Ks2[32][33];
    float (*Ts)[36] = (float(*)[36])Qs2;       // 18.4KB overlay, fits in Qs2

    int tid = threadIdx.x;
    int wid = tid >> 5, lane = tid & 31;
    int g = lane >> 2, t = lane & 3;
    int wm = wid & 3, wn = wid >> 2;
    int bh = blockIdx.z;
    int i0 = blockIdx.y * 128, j0 = blockIdx.x * 32;
    const uint2* Qhl = g_Qhl + (size_t)bh * Nn * HD;
    const uint2* Khl = g_Khl + (size_t)bh * Nn * HD;

    float acc[2][2][4] = {};
#pragma unroll
    for (int kc = 0; kc < HD; kc += 32) {
#pragma unroll
        for (int p = 0; p < 16; p++) {         // Q chunk 128x32 uint2
            int idx = p * 256 + tid;
            int m = idx >> 5, c = idx & 31;
            Qs2[m][c] = Qhl[(size_t)(i0 + m) * HD + kc + c];
        }
#pragma unroll
        for (int p = 0; p < 4; p++) {          // K chunk 32x32 uint2
            int idx = p * 256 + tid;
            int n = idx >> 5, c = idx & 31;
            Ks2[n][c] = Khl[(size_t)(j0 + n) * HD + kc + c];
        }
        __syncthreads();
#pragma unroll
        for (int ks = 0; ks < 4; ks++) {
            int k0 = ks * 8;
            unsigned ahi[2][4], alo[2][4], bhi[2][2], blo[2][2];
#pragma unroll
            for (int mt = 0; mt < 2; mt++) {
                int rb = 32 * wm + 16 * mt;
                uint2 q0 = Qs2[rb + g][k0 + t];
                uint2 q1 = Qs2[rb + g + 8][k0 + t];
                uint2 q2 = Qs2[rb + g][k0 + t + 4];
                uint2 q3 = Qs2[rb + g + 8][k0 + t + 4];
                ahi[mt][0] = q0.x; alo[mt][0] = q0.y;
                ahi[mt][1] = q1.x; alo[mt][1] = q1.y;
                ahi[mt][2] = q2.x; alo[mt][2] = q2.y;
                ahi[mt][3] = q3.x; alo[mt][3] = q3.y;
            }
#pragma unroll
            for (int nt = 0; nt < 2; nt++) {
                int nb = 16 * wn + 8 * nt;
                uint2 b0 = Ks2[nb + g][k0 + t];
                uint2 b1 = Ks2[nb + g][k0 + t + 4];
                bhi[nt][0] = b0.x; blo[nt][0] = b0.y;
                bhi[nt][1] = b1.x; blo[nt][1] = b1.y;
            }
#pragma unroll
            for (int mt = 0; mt < 2; mt++)
#pragma unroll
                for (int nt = 0; nt < 2; nt++) {
                    mma_tf32(acc[mt][nt], ahi[mt], blo[nt]);
                    mma_tf32(acc[mt][nt], alo[mt], bhi[nt]);
                    mma_tf32(acc[mt][nt], ahi[mt], bhi[nt]);
                }
        }
        __syncthreads();
    }

    // stage scaled result (R4-proven layout)
#pragma unroll
    for (int mt = 0; mt < 2; mt++)
#pragma unroll
        for (int nt = 0; nt < 2; nt++) {
            int r0 = 32 * wm + 16 * mt + g;
            int c0 = 16 * wn + 8 * nt + 2 * t;
            Ts[r0][c0]         = acc[mt][nt][0] * SCALEF;
            Ts[r0][c0 + 1]     = acc[mt][nt][1] * SCALEF;
            Ts[r0 + 8][c0]     = acc[mt][nt][2] * SCALEF;
            Ts[r0 + 8][c0 + 1] = acc[mt][nt][3] * SCALEF;
        }
    __syncthreads();

    float* attn = g_attn + ((size_t)bh * Nn + i0) * Nn + j0;
#pragma unroll
    for (int p = 0; p < 4; p++) {
        int idx = p * 256 + tid;
        int r = idx >> 3, cq = (idx & 7) * 4;
        *(float4*)&attn[(size_t)r * Nn + cq] = *(const float4*)&Ts[r][cq];
    }
    float* attnT = g_attnT + ((size_t)bh * Nn + j0) * Nn + i0;
#pragma unroll
    for (int p = 0; p < 16; p++) {
        int idx = p * 256 + tid;
        int jl = idx >> 7, il = idx & 127;
        attnT[(size_t)jl * Nn + il] = Ts[il][jl];
    }
}

// ---------------------------------------------------------------------------
// Kernel 3: exact K_TOP-th largest per row, warp-aggregated radix histogram.
// grid (BH*N, 2), block 256.
// ---------------------------------------------------------------------------
__global__ __launch_bounds__(256) void select_kernel() {
    __shared__ unsigned hist[4][256];
    __shared__ unsigned S[257];
    __shared__ unsigned s_sel, s_maxu;
    int tid = threadIdx.x;
    int lane = tid & 31;
    int hb = (tid >> 5) & 3;
    size_t row = blockIdx.x;
    int dir = blockIdx.y;
    const float* src = (dir ? g_attnT : g_attn) + row * Nn;

    unsigned u[8], lmax = 0u;
#pragma unroll
    for (int r = 0; r < 8; r++) {
        unsigned b = __float_as_uint(src[tid + 256 * r]);
        u[r] = b ^ ((unsigned)((int)b >> 31) | 0x80000000u);
        lmax = lmax > u[r] ? lmax : u[r];
    }
    if (tid == 0) s_maxu = 0u;

    unsigned prefix = 0u;
    int krem = KTOP;
#pragma unroll
    for (int pass = 0; pass < 4; pass++) {
        int shift = 24 - 8 * pass;
        hist[0][tid] = 0u; hist[1][tid] = 0u; hist[2][tid] = 0u; hist[3][tid] = 0u;
        __syncthreads();
        if (pass == 0) atomicMax(&s_maxu, lmax);
        unsigned himask = (pass == 0) ? 0u : (0xFFFFFFFFu << (shift + 8));
#pragma unroll
        for (int r = 0; r < 8; r++) {
            bool act = (u[r] & himask) == prefix;
            unsigned bin = act ? ((u[r] >> shift) & 255u) : 0xFFFFFFFFu;
            unsigned mk = __match_any_sync(0xFFFFFFFFu, bin);
            if (act && lane == (unsigned)(__ffs(mk) - 1))
                atomicAdd(&hist[hb][bin], (unsigned)__popc(mk));
        }
        __syncthreads();
        unsigned h = hist[0][tid] + hist[1][tid] + hist[2][tid] + hist[3][tid];
        hist[0][tid] = h;
        __syncthreads();
        if (tid < 32) {
            int base = tid * 8;
            unsigned c[8], loc[8];
#pragma unroll
            for (int j = 0; j < 8; j++) c[j] = hist[0][base + j];
            loc[7] = c[7];
#pragma unroll
            for (int j = 6; j >= 0; j--) loc[j] = c[j] + loc[j + 1];
            unsigned T = loc[0], incl = T;
#pragma unroll
            for (int off = 1; off < 32; off <<= 1) {
                unsigned v = __shfl_down_sync(0xFFFFFFFFu, incl, off);
                if (tid + off < 32) incl += v;
            }
            unsigned excl = incl - T;
#pragma unroll
            for (int j = 0; j < 8; j++) S[base + j] = excl + loc[j];
            if (tid == 0) S[256] = 0u;
        }
        __syncthreads();
        unsigned St = S[tid], St1 = S[tid + 1];
        if ((int)St >= krem && (int)St1 < krem) s_sel = (unsigned)tid;
        __syncthreads();
        unsigned sel = s_sel;
        krem -= (int)S[sel + 1];
        prefix |= sel << shift;
        __syncthreads();
    }
    if (tid == 0) {
        unsigned b = (prefix & 0x80000000u) ? (prefix ^ 0x80000000u) : ~prefix;
        float thr = __uint_as_float(b);
        if (dir) {
            g_cth[row] = thr;
        } else {
            g_rth[row] = thr;
            unsigned um = s_maxu;
            unsigned bm = (um & 0x80000000u) ? (um ^ 0x80000000u) : ~um;
            g_rmax[row] = __uint_as_float(bm);
        }
    }
}

// ---------------------------------------------------------------------------
// Kernel 4: fused masked softmax + P@V.  256 threads, tile 128 x 64, f32x2.
// Ps m-major stride 33 with SCALAR stores (alignment-safe, conflict-free reads).
// grid (N/128, BH).
// ---------------------------------------------------------------------------
__global__ __launch_bounds__(256) void spv_kernel() {
    __shared__ float Ps[128][33];
    __shared__ __align__(16) float Vs[32][68];
    __shared__ float s_rth[128], s_mx[128], s_cth[32];
    int tid = threadIdx.x;
    int tx = tid & 7, ty = tid >> 3;        // ty 0..31
    int bh = blockIdx.y;
    int i0 = blockIdx.x * 128;
    const float* V = g_Vh + (size_t)bh * Nn * HD;
    const float* A = g_attn + ((size_t)bh * Nn + i0) * Nn;
    if (tid < 128) {
        s_rth[tid] = g_rth[bh * Nn + i0 + tid];
        s_mx[tid]  = g_rmax[bh * Nn + i0 + tid];
    }
    __syncthreads();
    float rthr[4], mr[4], dloc[4];
#pragma unroll
    for (int i = 0; i < 4; i++) {
        rthr[i] = s_rth[4 * ty + i];
        mr[i]   = s_mx[4 * ty + i];
        dloc[i] = 0.f;
    }
    ull acc2[4][4] = {};

    for (int j0 = 0; j0 < Nn; j0 += 32) {
        float4 araw[4];
#pragma unroll
        for (int i = 0; i < 4; i++)
            araw[i] = *(const float4*)&A[(size_t)(4 * ty + i) * Nn + j0 + 4 * tx];
        __syncthreads();                   // prev chunk MMA done
        if (tid < 32) s_cth[tid] = g_cth[bh * Nn + j0 + tid];
#pragma unroll
        for (int p = 0; p < 2; p++) {      // V chunk 32x64
            int idx = p * 256 + tid;
            int jl = idx >> 4, d = (idx & 15) * 4;
            *(float4*)&Vs[jl][d] = *(const float4*)&V[(size_t)(j0 + jl) * HD + d];
        }
        __syncthreads();                   // cth + Vs visible
#pragma unroll
        for (int i = 0; i < 4; i++) {
            float av[4] = {araw[i].x, araw[i].y, araw[i].z, araw[i].w};
#pragma unroll
            for (int uu = 0; uu < 4; uu++) {
                float a = av[uu];
                float thr = fminf(rthr[i], s_cth[4 * tx + uu]);
                float p = (a >= thr) ? __expf(a - mr[i]) : 0.f;
                dloc[i] += p;
                Ps[4 * ty + i][4 * tx + uu] = p;     // scalar store, aligned
            }
        }
        __syncthreads();                   // Ps complete
#pragma unroll
        for (int kk = 0; kk < 32; kk++) {
            ull aB[4];
#pragma unroll
            for (int i = 0; i < 4; i++) {
                float a = Ps[4 * ty + i][kk];
                aB[i] = pack2(a, a);
            }
            ulonglong2 bb0 = *(const ulonglong2*)&Vs[kk][8 * tx];
            ulonglong2 bb1 = *(const ulonglong2*)&Vs[kk][8 * tx + 4];
            ull b2[4] = {bb0.x, bb0.y, bb1.x, bb1.y};
#pragma unroll
            for (int i = 0; i < 4; i++)
#pragma unroll
                for (int j = 0; j < 4; j++) ffma2(acc2[i][j], aB[i], b2[j]);
        }
    }
    // deterministic denominator over the 8 tx-lanes sharing each row
#pragma unroll
    for (int i = 0; i < 4; i++) {
        dloc[i] += __shfl_xor_sync(0xFFFFFFFFu, dloc[i], 1);
        dloc[i] += __shfl_xor_sync(0xFFFFFFFFu, dloc[i], 2);
        dloc[i] += __shfl_xor_sync(0xFFFFFFFFu, dloc[i], 4);
    }
#pragma unroll
    for (int i = 0; i < 4; i++) {
        float inv = 1.f / dloc[i];
        float o[8];
#pragma unroll
        for (int j = 0; j < 4; j++) {
            float2 uu = unpack2(acc2[i][j]);
            o[2 * j] = uu.x * inv; o[2 * j + 1] = uu.y * inv;
        }
        float* dst = &g_O[((size_t)bh * Nn + i0 + 4 * ty + i) * HD + 8 * tx];
        *(float4*)dst = make_float4(o[0], o[1], o[2], o[3]);
        *(float4*)(dst + 4) = make_float4(o[4], o[5], o[6], o[7]);
    }
}

// ---------------------------------------------------------------------------
// Kernel 5: output projection   (R2 proven)
// ---------------------------------------------------------------------------
__global__ __launch_bounds__(128) void outproj_kernel(const float* __restrict__ Wp,
                                                      const float* __restrict__ bp,
                                                      float* __restrict__ out) {
    __shared__ float As[128][33];
    __shared__ float Bs[64][33];
    int tid = threadIdx.x;
    int tx = tid & 7, ty = tid >> 3;
    int m0 = blockIdx.y * 128, n0 = blockIdx.x * 64;
    float acc[8][8] = {};
    for (int k0 = 0; k0 < Cc; k0 += 32) {
        int h = k0 >> 6;
#pragma unroll
        for (int l = tid; l < 1024; l += 128) {
            int m = l >> 3, c = (l & 7) * 4;
            int mg = m0 + m;
            int bb = mg >> 11, nl = mg & (Nn - 1);
            int d = (k0 + c) & 63;
            float4 v = *(const float4*)&g_O[(((size_t)(bb * Hh + h)) * Nn + nl) * HD + d];
            As[m][c] = v.x; As[m][c + 1] = v.y; As[m][c + 2] = v.z; As[m][c + 3] = v.w;
        }
#pragma unroll
        for (int l = tid; l < 512; l += 128) {
            int n = l >> 3, c = (l & 7) * 4;
            float4 v = *(const float4*)&Wp[(size_t)(n0 + n) * Cc + k0 + c];
            Bs[n][c] = v.x; Bs[n][c + 1] = v.y; Bs[n][c + 2] = v.z; Bs[n][c + 3] = v.w;
        }
        __syncthreads();
#pragma unroll
        for (int kk = 0; kk < 32; kk++) {
            float a[8], b[8];
#pragma unroll
            for (int i = 0; i < 8; i++) a[i] = As[8 * ty + i][kk];
#pragma unroll
            for (int j = 0; j < 8; j++) b[j] = Bs[8 * tx + j][kk];
#pragma unroll
            for (int i = 0; i < 8; i++)
#pragma unroll
                for (int j = 0; j < 8; j++) acc[i][j] += a[i] * b[j];
        }
        __syncthreads();
    }
#pragma unroll
    for (int i = 0; i < 8; i++) {
        int m = m0 + 8 * ty + i;
#pragma unroll
        for (int j = 0; j < 8; j++) {
            int n = n0 + 8 * tx + j;
            out[(size_t)m * Cc + n] = acc[i][j] + bp[n];
        }
    }
}

// ---------------------------------------------------------------------------
extern "C" void kernel_launch(void* const* d_in, const int* in_sizes, int n_in,
                              void* d_out, int out_size) {
    (void)in_sizes; (void)n_in; (void)out_size;
    const float* q   = (const float*)d_in[0];
    const float* k_v = (const float*)d_in[1];
    const float* Wq  = (const float*)d_in[2];
    const float* Wk  = (const float*)d_in[3];
    const float* Wv  = (const float*)d_in[4];
    const float* Wp  = (const float*)d_in[5];
    const float* bp  = (const float*)d_in[6];
    float* out = (float*)d_out;

    dim3 gproj(Cc / 64, (Bb * Nn) / 128);              // (8, 32)
    proj_kernel<<<gproj, 128>>>(q,   Wq, 0);
    proj_kernel<<<gproj, 128>>>(k_v, Wk, 1);
    proj_kernel<<<gproj, 128>>>(k_v, Wv, 2);

    dim3 gqk(Nn / 32, Nn / 128, BH);                   // (64, 16, 16)
    qk_tc_kernel<<<gqk, 256>>>();

    dim3 gsel(BH * Nn, 2);
    select_kernel<<<gsel, 256>>>();

    dim3 gspv(Nn / 128, BH);                           // (16, 16)
    spv_kernel<<<gspv, 256>>>();

    dim3 gout(Cc / 64, (Bb * Nn) / 128);
    outproj_kernel<<<gout, 128>>>(Wp, bp, out);
}

// round 7
// speedup vs baseline: 1.1635x; 1.1635x over previous
#include <cuda_runtime.h>
#include <cstdint>

#define Bb   2
#define Nn   2048
#define Cc   512
#define Hh   8
#define HD   64
#define BH   16
#define KTOP 1024
#define SCALEF 0.125f

// ---------------- scratch ----------------
__device__ uint2 g_Qhl[BH * Nn * HD];                // packed (tf32 hi, tf32 lo)
__device__ uint2 g_Khl[BH * Nn * HD];
__device__ float g_Vh[BH * Nn * HD];
__device__ float g_attn[(size_t)BH * Nn * Nn];
__device__ float g_attnT[(size_t)BH * Nn * Nn];
__device__ float g_rth[BH * Nn];
__device__ float g_cth[BH * Nn];
__device__ float g_rmax[BH * Nn];
__device__ float g_O[BH * Nn * HD];

// ---------------- helpers ----------------
__device__ __forceinline__ unsigned tf32_rna(float x) {
    unsigned u; asm("cvt.rna.tf32.f32 %0, %1;" : "=r"(u) : "f"(x)); return u;
}
__device__ __forceinline__ uint2 split_tf32(float x) {
    unsigned hi = tf32_rna(x);
    unsigned lo = tf32_rna(x - __uint_as_float(hi));
    return make_uint2(hi, lo);
}
__device__ __forceinline__ void mma_tf32(float* c, const unsigned* a, const unsigned* b) {
    asm("mma.sync.aligned.m16n8k8.row.col.f32.tf32.tf32.f32 "
        "{%0,%1,%2,%3},{%4,%5,%6,%7},{%8,%9},{%0,%1,%2,%3};"
        : "+f"(c[0]), "+f"(c[1]), "+f"(c[2]), "+f"(c[3])
        : "r"(a[0]), "r"(a[1]), "r"(a[2]), "r"(a[3]), "r"(b[0]), "r"(b[1]));
}

// ---------------------------------------------------------------------------
// Kernel 1: projections  out = X @ W^T.  which: 0=Q(hi/lo) 1=K(hi/lo) 2=V(f32)
// tile 128x64, 128 threads, 8x8 per thread (R2 proven core)
// ---------------------------------------------------------------------------
__global__ __launch_bounds__(128) void proj_kernel(const float* __restrict__ X,
                                                   const float* __restrict__ W,
                                                   int which) {
    __shared__ float As[128][33];
    __shared__ float Bs[64][33];
    int tid = threadIdx.x;
    int tx = tid & 7, ty = tid >> 3;
    int m0 = blockIdx.y * 128, n0 = blockIdx.x * 64;
    float acc[8][8] = {};
    for (int k0 = 0; k0 < Cc; k0 += 32) {
#pragma unroll
        for (int l = tid; l < 1024; l += 128) {
            int m = l >> 3, c = (l & 7) * 4;
            float4 v = *(const float4*)&X[(size_t)(m0 + m) * Cc + k0 + c];
            As[m][c] = v.x; As[m][c + 1] = v.y; As[m][c + 2] = v.z; As[m][c + 3] = v.w;
        }
#pragma unroll
        for (int l = tid; l < 512; l += 128) {
            int n = l >> 3, c = (l & 7) * 4;
            float4 v = *(const float4*)&W[(size_t)(n0 + n) * Cc + k0 + c];
            Bs[n][c] = v.x; Bs[n][c + 1] = v.y; Bs[n][c + 2] = v.z; Bs[n][c + 3] = v.w;
        }
        __syncthreads();
#pragma unroll
        for (int kk = 0; kk < 32; kk++) {
            float a[8], b[8];
#pragma unroll
            for (int i = 0; i < 8; i++) a[i] = As[8 * ty + i][kk];
#pragma unroll
            for (int j = 0; j < 8; j++) b[j] = Bs[8 * tx + j][kk];
#pragma unroll
            for (int i = 0; i < 8; i++)
#pragma unroll
                for (int j = 0; j < 8; j++) acc[i][j] += a[i] * b[j];
        }
        __syncthreads();
    }
#pragma unroll
    for (int i = 0; i < 8; i++) {
        int m = m0 + 8 * ty + i;
        int bb = m >> 11, nl = m & (Nn - 1);
#pragma unroll
        for (int j = 0; j < 8; j++) {
            int n = n0 + 8 * tx + j;
            int h = n >> 6, d = n & 63;
            size_t idx = (((size_t)(bb * Hh + h)) * Nn + nl) * HD + d;
            if (which == 2)       g_Vh[idx]  = acc[i][j];
            else if (which == 0)  g_Qhl[idx] = split_tf32(acc[i][j]);
            else                  g_Khl[idx] = split_tf32(acc[i][j]);
        }
    }
}

// ---------------------------------------------------------------------------
// Kernel 2: attn = scale * Q K^T via 3xTF32 mma.sync on PRE-SPLIT operands.
// Block 256, tile M=128 x N=32, K chunks of 32.
// uint2 smem stride 36 (72 words, 72 % 32 == 8): fragment-load banks are
// 8g+2t -> 16 distinct bank-pairs per LDS.64 phase. CONFLICT-FREE.
// Ts overlay stride 36 floats (144B rows, float4-aligned; R4-proven epilogue).
// ---------------------------------------------------------------------------
__global__ __launch_bounds__(256) void qk_tc_kernel() {
    __shared__ __align__(16) uint2 Qs2[128][36];   // 36.9KB
    __shared__ __align__(16) uint2 Ks2[32][36];    //  9.2KB
    float (*Ts)[36] = (float(*)[36])Qs2;           // 18.4KB overlay

    int tid = threadIdx.x;
    int wid = tid >> 5, lane = tid & 31;
    int g = lane >> 2, t = lane & 3;
    int wm = wid & 3, wn = wid >> 2;
    int bh = blockIdx.z;
    int i0 = blockIdx.y * 128, j0 = blockIdx.x * 32;
    const uint2* Qhl = g_Qhl + (size_t)bh * Nn * HD;
    const uint2* Khl = g_Khl + (size_t)bh * Nn * HD;

    float acc[2][2][4] = {};
#pragma unroll
    for (int kc = 0; kc < HD; kc += 32) {
#pragma unroll 4
        for (int p = 0; p < 16; p++) {         // Q chunk 128x32 uint2
            int idx = p * 256 + tid;
            int m = idx >> 5, c = idx & 31;
            Qs2[m][c] = Qhl[(size_t)(i0 + m) * HD + kc + c];
        }
#pragma unroll
        for (int p = 0; p < 4; p++) {          // K chunk 32x32 uint2
            int idx = p * 256 + tid;
            int n = idx >> 5, c = idx & 31;
            Ks2[n][c] = Khl[(size_t)(j0 + n) * HD + kc + c];
        }
        __syncthreads();
#pragma unroll
        for (int ks = 0; ks < 4; ks++) {
            int k0 = ks * 8;
            unsigned ahi[2][4], alo[2][4], bhi[2][2], blo[2][2];
#pragma unroll
            for (int mt = 0; mt < 2; mt++) {
                int rb = 32 * wm + 16 * mt;
                uint2 q0 = Qs2[rb + g][k0 + t];
                uint2 q1 = Qs2[rb + g + 8][k0 + t];
                uint2 q2 = Qs2[rb + g][k0 + t + 4];
                uint2 q3 = Qs2[rb + g + 8][k0 + t + 4];
                ahi[mt][0] = q0.x; alo[mt][0] = q0.y;
                ahi[mt][1] = q1.x; alo[mt][1] = q1.y;
                ahi[mt][2] = q2.x; alo[mt][2] = q2.y;
                ahi[mt][3] = q3.x; alo[mt][3] = q3.y;
            }
#pragma unroll
            for (int nt = 0; nt < 2; nt++) {
                int nb = 16 * wn + 8 * nt;
                uint2 b0 = Ks2[nb + g][k0 + t];
                uint2 b1 = Ks2[nb + g][k0 + t + 4];
                bhi[nt][0] = b0.x; blo[nt][0] = b0.y;
                bhi[nt][1] = b1.x; blo[nt][1] = b1.y;
            }
#pragma unroll
            for (int mt = 0; mt < 2; mt++)
#pragma unroll
                for (int nt = 0; nt < 2; nt++) {
                    mma_tf32(acc[mt][nt], ahi[mt], blo[nt]);
                    mma_tf32(acc[mt][nt], alo[mt], bhi[nt]);
                    mma_tf32(acc[mt][nt], ahi[mt], bhi[nt]);
                }
        }
        __syncthreads();
    }

    // stage scaled result (R4-proven layout)
#pragma unroll
    for (int mt = 0; mt < 2; mt++)
#pragma unroll
        for (int nt = 0; nt < 2; nt++) {
            int r0 = 32 * wm + 16 * mt + g;
            int c0 = 16 * wn + 8 * nt + 2 * t;
            Ts[r0][c0]         = acc[mt][nt][0] * SCALEF;
            Ts[r0][c0 + 1]     = acc[mt][nt][1] * SCALEF;
            Ts[r0 + 8][c0]     = acc[mt][nt][2] * SCALEF;
            Ts[r0 + 8][c0 + 1] = acc[mt][nt][3] * SCALEF;
        }
    __syncthreads();

    float* attn = g_attn + ((size_t)bh * Nn + i0) * Nn + j0;
#pragma unroll
    for (int p = 0; p < 4; p++) {
        int idx = p * 256 + tid;
        int r = idx >> 3, cq = (idx & 7) * 4;
        *(float4*)&attn[(size_t)r * Nn + cq] = *(const float4*)&Ts[r][cq];
    }
    float* attnT = g_attnT + ((size_t)bh * Nn + j0) * Nn + i0;
#pragma unroll
    for (int p = 0; p < 16; p++) {
        int idx = p * 256 + tid;
        int jl = idx >> 7, il = idx & 127;
        attnT[(size_t)jl * Nn + il] = Ts[il][jl];
    }
}

// ---------------------------------------------------------------------------
// Kernel 3: exact K_TOP-th largest per row, warp-aggregated radix histogram.
// grid (BH*N, 2), block 256.
// ---------------------------------------------------------------------------
__global__ __launch_bounds__(256) void select_kernel() {
    __shared__ unsigned hist[4][256];
    __shared__ unsigned S[257];
    __shared__ unsigned s_sel, s_maxu;
    int tid = threadIdx.x;
    int lane = tid & 31;
    int hb = (tid >> 5) & 3;
    size_t row = blockIdx.x;
    int dir = blockIdx.y;
    const float* src = (dir ? g_attnT : g_attn) + row * Nn;

    unsigned u[8], lmax = 0u;
#pragma unroll
    for (int r = 0; r < 8; r++) {
        unsigned b = __float_as_uint(src[tid + 256 * r]);
        u[r] = b ^ ((unsigned)((int)b >> 31) | 0x80000000u);
        lmax = lmax > u[r] ? lmax : u[r];
    }
    if (tid == 0) s_maxu = 0u;

    unsigned prefix = 0u;
    int krem = KTOP;
#pragma unroll
    for (int pass = 0; pass < 4; pass++) {
        int shift = 24 - 8 * pass;
        hist[0][tid] = 0u; hist[1][tid] = 0u; hist[2][tid] = 0u; hist[3][tid] = 0u;
        __syncthreads();
        if (pass == 0) atomicMax(&s_maxu, lmax);
        unsigned himask = (pass == 0) ? 0u : (0xFFFFFFFFu << (shift + 8));
#pragma unroll
        for (int r = 0; r < 8; r++) {
            bool act = (u[r] & himask) == prefix;
            unsigned bin = act ? ((u[r] >> shift) & 255u) : 0xFFFFFFFFu;
            unsigned mk = __match_any_sync(0xFFFFFFFFu, bin);
            if (act && lane == (unsigned)(__ffs(mk) - 1))
                atomicAdd(&hist[hb][bin], (unsigned)__popc(mk));
        }
        __syncthreads();
        unsigned h = hist[0][tid] + hist[1][tid] + hist[2][tid] + hist[3][tid];
        hist[0][tid] = h;
        __syncthreads();
        if (tid < 32) {
            int base = tid * 8;
            unsigned c[8], loc[8];
#pragma unroll
            for (int j = 0; j < 8; j++) c[j] = hist[0][base + j];
            loc[7] = c[7];
#pragma unroll
            for (int j = 6; j >= 0; j--) loc[j] = c[j] + loc[j + 1];
            unsigned T = loc[0], incl = T;
#pragma unroll
            for (int off = 1; off < 32; off <<= 1) {
                unsigned v = __shfl_down_sync(0xFFFFFFFFu, incl, off);
                if (tid + off < 32) incl += v;
            }
            unsigned excl = incl - T;
#pragma unroll
            for (int j = 0; j < 8; j++) S[base + j] = excl + loc[j];
            if (tid == 0) S[256] = 0u;
        }
        __syncthreads();
        unsigned St = S[tid], St1 = S[tid + 1];
        if ((int)St >= krem && (int)St1 < krem) s_sel = (unsigned)tid;
        __syncthreads();
        unsigned sel = s_sel;
        krem -= (int)S[sel + 1];
        prefix |= sel << shift;
        __syncthreads();
    }
    if (tid == 0) {
        unsigned b = (prefix & 0x80000000u) ? (prefix ^ 0x80000000u) : ~prefix;
        float thr = __uint_as_float(b);
        if (dir) {
            g_cth[row] = thr;
        } else {
            g_rth[row] = thr;
            unsigned um = s_maxu;
            unsigned bm = (um & 0x80000000u) ? (um ^ 0x80000000u) : ~um;
            g_rmax[row] = __uint_as_float(bm);
        }
    }
}

// ---------------------------------------------------------------------------
// Kernel 4: fused masked softmax + P@V   (exact R4-proven version)
// ---------------------------------------------------------------------------
__global__ __launch_bounds__(128) void spv_kernel() {
    __shared__ float Ps[128][33];
    __shared__ float Vs[32][68];
    __shared__ float s_rth[128], s_mx[128], s_cth[32], s_den[128];
    int tid = threadIdx.x;
    int tx = tid & 7, ty = tid >> 3;
    int bh = blockIdx.y;
    int i0 = blockIdx.x * 128;
    const float* V = g_Vh + (size_t)bh * Nn * HD;
    const float* A = g_attn + ((size_t)bh * Nn + i0) * Nn;
    s_rth[tid] = g_rth[bh * Nn + i0 + tid];
    s_mx[tid]  = g_rmax[bh * Nn + i0 + tid];
    s_den[tid] = 0.f;
    __syncthreads();
    float rthr[8], mr[8], dloc[8];
#pragma unroll
    for (int i = 0; i < 8; i++) {
        rthr[i] = s_rth[8 * ty + i];
        mr[i]   = s_mx[8 * ty + i];
        dloc[i] = 0.f;
    }
    float acc[8][8] = {};

    for (int j0 = 0; j0 < Nn; j0 += 32) {
        float4 araw[8];
#pragma unroll
        for (int i = 0; i < 8; i++)
            araw[i] = *(const float4*)&A[(size_t)(8 * ty + i) * Nn + j0 + 4 * tx];
        __syncthreads();
        if (tid < 32) s_cth[tid] = g_cth[bh * Nn + j0 + tid];
#pragma unroll
        for (int l = tid; l < 512; l += 128) {
            int jl = l >> 4, d = (l & 15) * 4;
            *(float4*)&Vs[jl][d] = *(const float4*)&V[(size_t)(j0 + jl) * HD + d];
        }
        __syncthreads();
#pragma unroll
        for (int i = 0; i < 8; i++) {
            float av[4] = {araw[i].x, araw[i].y, araw[i].z, araw[i].w};
#pragma unroll
            for (int uu = 0; uu < 4; uu++) {
                float a = av[uu];
                float thr = fminf(rthr[i], s_cth[4 * tx + uu]);
                float p = (a >= thr) ? __expf(a - mr[i]) : 0.f;
                dloc[i] += p;
                Ps[8 * ty + i][4 * tx + uu] = p;
            }
        }
        __syncthreads();
#pragma unroll
        for (int kk = 0; kk < 32; kk++) {
            float a[8], b[8];
#pragma unroll
            for (int i = 0; i < 8; i++) a[i] = Ps[8 * ty + i][kk];
            float4 b0 = *(const float4*)&Vs[kk][8 * tx];
            float4 b1 = *(const float4*)&Vs[kk][8 * tx + 4];
            b[0] = b0.x; b[1] = b0.y; b[2] = b0.z; b[3] = b0.w;
            b[4] = b1.x; b[5] = b1.y; b[6] = b1.z; b[7] = b1.w;
#pragma unroll
            for (int i = 0; i < 8; i++)
#pragma unroll
                for (int j = 0; j < 8; j++) acc[i][j] += a[i] * b[j];
        }
    }
#pragma unroll
    for (int i = 0; i < 8; i++) atomicAdd(&s_den[8 * ty + i], dloc[i]);
    __syncthreads();
#pragma unroll
    for (int i = 0; i < 8; i++) {
        int il = 8 * ty + i;
        float inv = 1.f / s_den[il];
        float4 v0 = make_float4(acc[i][0] * inv, acc[i][1] * inv, acc[i][2] * inv, acc[i][3] * inv);
        float4 v1 = make_float4(acc[i][4] * inv, acc[i][5] * inv, acc[i][6] * inv, acc[i][7] * inv);
        float* o = &g_O[((size_t)bh * Nn + i0 + il) * HD + 8 * tx];
        *(float4*)o = v0;
        *(float4*)(o + 4) = v1;
    }
}

// ---------------------------------------------------------------------------
// Kernel 5: output projection   (R2 proven)
// ---------------------------------------------------------------------------
__global__ __launch_bounds__(128) void outproj_kernel(const float* __restrict__ Wp,
                                                      const float* __restrict__ bp,
                                                      float* __restrict__ out) {
    __shared__ float As[128][33];
    __shared__ float Bs[64][33];
    int tid = threadIdx.x;
    int tx = tid & 7, ty = tid >> 3;
    int m0 = blockIdx.y * 128, n0 = blockIdx.x * 64;
    float acc[8][8] = {};
    for (int k0 = 0; k0 < Cc; k0 += 32) {
        int h = k0 >> 6;
#pragma unroll
        for (int l = tid; l < 1024; l += 128) {
            int m = l >> 3, c = (l & 7) * 4;
            int mg = m0 + m;
            int bb = mg >> 11, nl = mg & (Nn - 1);
            int d = (k0 + c) & 63;
            float4 v = *(const float4*)&g_O[(((size_t)(bb * Hh + h)) * Nn + nl) * HD + d];
            As[m][c] = v.x; As[m][c + 1] = v.y; As[m][c + 2] = v.z; As[m][c + 3] = v.w;
        }
#pragma unroll
        for (int l = tid; l < 512; l += 128) {
            int n = l >> 3, c = (l & 7) * 4;
            float4 v = *(const float4*)&Wp[(size_t)(n0 + n) * Cc + k0 + c];
            Bs[n][c] = v.x; Bs[n][c + 1] = v.y; Bs[n][c + 2] = v.z; Bs[n][c + 3] = v.w;
        }
        __syncthreads();
#pragma unroll
        for (int kk = 0; kk < 32; kk++) {
            float a[8], b[8];
#pragma unroll
            for (int i = 0; i < 8; i++) a[i] = As[8 * ty + i][kk];
#pragma unroll
            for (int j = 0; j < 8; j++) b[j] = Bs[8 * tx + j][kk];
#pragma unroll
            for (int i = 0; i < 8; i++)
#pragma unroll
                for (int j = 0; j < 8; j++) acc[i][j] += a[i] * b[j];
        }
        __syncthreads();
    }
#pragma unroll
    for (int i = 0; i < 8; i++) {
        int m = m0 + 8 * ty + i;
#pragma unroll
        for (int j = 0; j < 8; j++) {
            int n = n0 + 8 * tx + j;
            out[(size_t)m * Cc + n] = acc[i][j] + bp[n];
        }
    }
}

// ---------------------------------------------------------------------------
extern "C" void kernel_launch(void* const* d_in, const int* in_sizes, int n_in,
                              void* d_out, int out_size) {
    (void)in_sizes; (void)n_in; (void)out_size;
    const float* q   = (const float*)d_in[0];
    const float* k_v = (const float*)d_in[1];
    const float* Wq  = (const float*)d_in[2];
    const float* Wk  = (const float*)d_in[3];
    const float* Wv  = (const float*)d_in[4];
    const float* Wp  = (const float*)d_in[5];
    const float* bp  = (const float*)d_in[6];
    float* out = (float*)d_out;

    dim3 gproj(Cc / 64, (Bb * Nn) / 128);              // (8, 32)
    proj_kernel<<<gproj, 128>>>(q,   Wq, 0);
    proj_kernel<<<gproj, 128>>>(k_v, Wk, 1);
    proj_kernel<<<gproj, 128>>>(k_v, Wv, 2);

    dim3 gqk(Nn / 32, Nn / 128, BH);                   // (64, 16, 16)
    qk_tc_kernel<<<gqk, 256>>>();

    dim3 gsel(BH * Nn, 2);
    select_kernel<<<gsel, 256>>>();

    dim3 gspv(Nn / 128, BH);                           // (16, 16)
    spv_kernel<<<gspv, 128>>>();

    dim3 gout(Cc / 64, (Bb * Nn) / 128);
    outproj_kernel<<<gout, 128>>>(Wp, bp, out);
}

// round 9
// speedup vs baseline: 1.3565x; 1.1659x over previous
#include <cuda_runtime.h>
#include <cstdint>

#define Bb   2
#define Nn   2048
#define Cc   512
#define Hh   8
#define HD   64
#define BH   16
#define KTOP 1024
#define SCALEF 0.125f

// ---------------- scratch ----------------
__device__ float g_Qh[BH * Nn * HD];
__device__ float g_Kh[BH * Nn * HD];
__device__ float g_Vh[BH * Nn * HD];
__device__ float g_attn[(size_t)BH * Nn * Nn];
__device__ float g_attnT[(size_t)BH * Nn * Nn];
__device__ float g_rth[BH * Nn];
__device__ float g_cth[BH * Nn];
__device__ float g_rmax[BH * Nn];
__device__ float g_O[BH * Nn * HD];

// ---------------- tf32 helpers ----------------
__device__ __forceinline__ unsigned tf32_rna(float x) {
    unsigned u; asm("cvt.rna.tf32.f32 %0, %1;" : "=r"(u) : "f"(x)); return u;
}
__device__ __forceinline__ void split_tf32(float x, unsigned& hi, unsigned& lo) {
    hi = tf32_rna(x);
    float hf = __uint_as_float(hi);
    lo = tf32_rna(x - hf);
}
__device__ __forceinline__ uint2 split2_tf32(float x) {
    unsigned hi, lo; split_tf32(x, hi, lo); return make_uint2(hi, lo);
}
__device__ __forceinline__ void mma_tf32(float* c, const unsigned* a, const unsigned* b) {
    asm("mma.sync.aligned.m16n8k8.row.col.f32.tf32.tf32.f32 "
        "{%0,%1,%2,%3},{%4,%5,%6,%7},{%8,%9},{%0,%1,%2,%3};"
        : "+f"(c[0]), "+f"(c[1]), "+f"(c[2]), "+f"(c[3])
        : "r"(a[0]), "r"(a[1]), "r"(a[2]), "r"(a[3]), "r"(b[0]), "r"(b[1]));
}

// ---------------------------------------------------------------------------
// Kernel 1: projections  out = X @ W^T  scattered to [B,H,N,HD]   (R4 exact)
// ---------------------------------------------------------------------------
__global__ __launch_bounds__(128) void proj_kernel(const float* __restrict__ X,
                                                   const float* __restrict__ W,
                                                   int which) {
    __shared__ float As[128][33];
    __shared__ float Bs[64][33];
    int tid = threadIdx.x;
    int tx = tid & 7, ty = tid >> 3;
    int m0 = blockIdx.y * 128, n0 = blockIdx.x * 64;
    float acc[8][8] = {};
    for (int k0 = 0; k0 < Cc; k0 += 32) {
#pragma unroll
        for (int l = tid; l < 1024; l += 128) {
            int m = l >> 3, c = (l & 7) * 4;
            float4 v = *(const float4*)&X[(size_t)(m0 + m) * Cc + k0 + c];
            As[m][c] = v.x; As[m][c + 1] = v.y; As[m][c + 2] = v.z; As[m][c + 3] = v.w;
        }
#pragma unroll
        for (int l = tid; l < 512; l += 128) {
            int n = l >> 3, c = (l & 7) * 4;
            float4 v = *(const float4*)&W[(size_t)(n0 + n) * Cc + k0 + c];
            Bs[n][c] = v.x; Bs[n][c + 1] = v.y; Bs[n][c + 2] = v.z; Bs[n][c + 3] = v.w;
        }
        __syncthreads();
#pragma unroll
        for (int kk = 0; kk < 32; kk++) {
            float a[8], b[8];
#pragma unroll
            for (int i = 0; i < 8; i++) a[i] = As[8 * ty + i][kk];
#pragma unroll
            for (int j = 0; j < 8; j++) b[j] = Bs[8 * tx + j][kk];
#pragma unroll
            for (int i = 0; i < 8; i++)
#pragma unroll
                for (int j = 0; j < 8; j++) acc[i][j] += a[i] * b[j];
        }
        __syncthreads();
    }
    float* out = (which == 0) ? g_Qh : ((which == 1) ? g_Kh : g_Vh);
#pragma unroll
    for (int i = 0; i < 8; i++) {
        int m = m0 + 8 * ty + i;
        int bb = m >> 11, nl = m & (Nn - 1);
#pragma unroll
        for (int j = 0; j < 8; j++) {
            int n = n0 + 8 * tx + j;
            int h = n >> 6, d = n & 63;
            out[(((size_t)(bb * Hh + h)) * Nn + nl) * HD + d] = acc[i][j];
        }
    }
}

// ---------------------------------------------------------------------------
// Kernel 2: attn = scale * Q K^T via 3xTF32 mma.sync   (R4 exact, 269us proven)
// ---------------------------------------------------------------------------
__global__ __launch_bounds__(256) void qk_tc_kernel() {
    __shared__ float Qs[128][68];
    __shared__ float Ks[32][68];
    float (*Ts)[36] = (float(*)[36])Qs;

    int tid = threadIdx.x;
    int wid = tid >> 5, lane = tid & 31;
    int g = lane >> 2, t = lane & 3;
    int wm = wid & 3, wn = wid >> 2;
    int bh = blockIdx.z;
    int i0 = blockIdx.y * 128, j0 = blockIdx.x * 32;
    const float* Q = g_Qh + (size_t)bh * Nn * HD;
    const float* K = g_Kh + (size_t)bh * Nn * HD;

#pragma unroll
    for (int p = 0; p < 8; p++) {
        int idx = p * 256 + tid;
        int m = idx >> 4, c = (idx & 15) * 4;
        float4 v = *(const float4*)&Q[(size_t)(i0 + m) * HD + c];
        *(float4*)&Qs[m][c] = v;
    }
#pragma unroll
    for (int p = 0; p < 2; p++) {
        int idx = p * 256 + tid;
        int n = idx >> 4, c = (idx & 15) * 4;
        float4 v = *(const float4*)&K[(size_t)(j0 + n) * HD + c];
        *(float4*)&Ks[n][c] = v;
    }
    __syncthreads();

    float acc[2][2][4] = {};
#pragma unroll
    for (int ks = 0; ks < 8; ks++) {
        int k0 = ks * 8;
        unsigned ahi[2][4], alo[2][4], bhi[2][2], blo[2][2];
#pragma unroll
        for (int mt = 0; mt < 2; mt++) {
            int rb = 32 * wm + 16 * mt;
            float x0 = Qs[rb + g][k0 + t];
            float x1 = Qs[rb + g + 8][k0 + t];
            float x2 = Qs[rb + g][k0 + t + 4];
            float x3 = Qs[rb + g + 8][k0 + t + 4];
            split_tf32(x0, ahi[mt][0], alo[mt][0]);
            split_tf32(x1, ahi[mt][1], alo[mt][1]);
            split_tf32(x2, ahi[mt][2], alo[mt][2]);
            split_tf32(x3, ahi[mt][3], alo[mt][3]);
        }
#pragma unroll
        for (int nt = 0; nt < 2; nt++) {
            int nb = 16 * wn + 8 * nt;
            float y0 = Ks[nb + g][k0 + t];
            float y1 = Ks[nb + g][k0 + t + 4];
            split_tf32(y0, bhi[nt][0], blo[nt][0]);
            split_tf32(y1, bhi[nt][1], blo[nt][1]);
        }
#pragma unroll
        for (int mt = 0; mt < 2; mt++)
#pragma unroll
            for (int nt = 0; nt < 2; nt++) {
                mma_tf32(acc[mt][nt], ahi[mt], blo[nt]);
                mma_tf32(acc[mt][nt], alo[mt], bhi[nt]);
                mma_tf32(acc[mt][nt], ahi[mt], bhi[nt]);
            }
    }
    __syncthreads();

#pragma unroll
    for (int mt = 0; mt < 2; mt++)
#pragma unroll
        for (int nt = 0; nt < 2; nt++) {
            int r0 = 32 * wm + 16 * mt + g;
            int c0 = 16 * wn + 8 * nt + 2 * t;
            Ts[r0][c0]         = acc[mt][nt][0] * SCALEF;
            Ts[r0][c0 + 1]     = acc[mt][nt][1] * SCALEF;
            Ts[r0 + 8][c0]     = acc[mt][nt][2] * SCALEF;
            Ts[r0 + 8][c0 + 1] = acc[mt][nt][3] * SCALEF;
        }
    __syncthreads();

    float* attn = g_attn + ((size_t)bh * Nn + i0) * Nn + j0;
#pragma unroll
    for (int p = 0; p < 4; p++) {
        int idx = p * 256 + tid;
        int r = idx >> 3, cq = (idx & 7) * 4;
        *(float4*)&attn[(size_t)r * Nn + cq] = *(const float4*)&Ts[r][cq];
    }
    float* attnT = g_attnT + ((size_t)bh * Nn + j0) * Nn + i0;
#pragma unroll
    for (int p = 0; p < 16; p++) {
        int idx = p * 256 + tid;
        int jl = idx >> 7, il = idx & 127;
        attnT[(size_t)jl * Nn + il] = Ts[il][jl];
    }
}

// ---------------------------------------------------------------------------
// Kernel 3: exact K_TOP-th largest per row (radix select)   (R2/R4 exact)
// ---------------------------------------------------------------------------
__global__ __launch_bounds__(256) void select_kernel() {
    __shared__ unsigned hist[4][256];
    __shared__ unsigned S[257];
    __shared__ unsigned s_sel, s_maxu;
    int tid = threadIdx.x;
    size_t row = blockIdx.x;
    int dir = blockIdx.y;
    const float* src = (dir ? g_attnT : g_attn) + row * Nn;

    unsigned u[8], lmax = 0u;
#pragma unroll
    for (int r = 0; r < 8; r++) {
        unsigned b = __float_as_uint(src[tid + 256 * r]);
        u[r] = b ^ ((unsigned)((int)b >> 31) | 0x80000000u);
        lmax = lmax > u[r] ? lmax : u[r];
    }
    if (tid == 0) s_maxu = 0u;

    unsigned prefix = 0u;
    int krem = KTOP;
    int hb = tid >> 6;
#pragma unroll
    for (int pass = 0; pass < 4; pass++) {
        int shift = 24 - 8 * pass;
        hist[0][tid] = 0u; hist[1][tid] = 0u; hist[2][tid] = 0u; hist[3][tid] = 0u;
        __syncthreads();
        if (pass == 0) atomicMax(&s_maxu, lmax);
        unsigned himask = (pass == 0) ? 0u : (0xFFFFFFFFu << (shift + 8));
#pragma unroll
        for (int r = 0; r < 8; r++)
            if ((u[r] & himask) == prefix)
                atomicAdd(&hist[hb][(u[r] >> shift) & 255u], 1u);
        __syncthreads();
        unsigned h = hist[0][tid] + hist[1][tid] + hist[2][tid] + hist[3][tid];
        hist[0][tid] = h;
        __syncthreads();
        if (tid < 32) {
            int base = tid * 8;
            unsigned c[8], loc[8];
#pragma unroll
            for (int j = 0; j < 8; j++) c[j] = hist[0][base + j];
            loc[7] = c[7];
#pragma unroll
            for (int j = 6; j >= 0; j--) loc[j] = c[j] + loc[j + 1];
            unsigned T = loc[0], incl = T;
#pragma unroll
            for (int off = 1; off < 32; off <<= 1) {
                unsigned v = __shfl_down_sync(0xFFFFFFFFu, incl, off);
                if (tid + off < 32) incl += v;
            }
            unsigned excl = incl - T;
#pragma unroll
            for (int j = 0; j < 8; j++) S[base + j] = excl + loc[j];
            if (tid == 0) S[256] = 0u;
        }
        __syncthreads();
        unsigned St = S[tid], St1 = S[tid + 1];
        if ((int)St >= krem && (int)St1 < krem) s_sel = (unsigned)tid;
        __syncthreads();
        unsigned sel = s_sel;
        krem -= (int)S[sel + 1];
        prefix |= sel << shift;
        __syncthreads();
    }
    if (tid == 0) {
        unsigned b = (prefix & 0x80000000u) ? (prefix ^ 0x80000000u) : ~prefix;
        float thr = __uint_as_float(b);
        if (dir) {
            g_cth[row] = thr;
        } else {
            g_rth[row] = thr;
            unsigned um = s_maxu;
            unsigned bm = (um & 0x80000000u) ? (um ^ 0x80000000u) : ~um;
            g_rmax[row] = __uint_as_float(bm);
        }
    }
}

// ---------------------------------------------------------------------------
// Kernel 4: fused masked softmax + P@V via 3xTF32 mma.sync.
// 256 threads, tile 64 rows x 64 HD, token chunks of 32.  grid (N/64, BH).
// Ps2[64][36] uint2 (stride 36 = 4 mod 16: conflict-free A-frag LDS.64).
// Vs2[32][68] uint2 [token][d] (stride 68 = 4 mod 16: conflict-free B-frag;
// holds the FULL 64 d-columns — the R8 bug was a 36-col stride here).
// Warps: wm = wid&1 (32 rows, mt 0..1), wn = wid>>1 (16 cols, nt 0..1).
// ---------------------------------------------------------------------------
__global__ __launch_bounds__(256) void spv_tc_kernel() {
    __shared__ __align__(16) uint2 Ps2[64][36];    // 18.4KB
    __shared__ __align__(16) uint2 Vs2[32][68];    // 17.4KB
    __shared__ float s_rth[64], s_mx[64], s_den[64], s_cth[32];

    int tid = threadIdx.x;
    int tx = tid & 7, ty = tid >> 3;              // exp-phase map (ty 0..31)
    int wid = tid >> 5, lane = tid & 31;
    int g = lane >> 2, t = lane & 3;
    int wm = wid & 1, wn = wid >> 1;              // wm 0..1, wn 0..3
    int bh = blockIdx.y;
    int i0 = blockIdx.x * 64;
    const float* V = g_Vh + (size_t)bh * Nn * HD;
    const float* A = g_attn + ((size_t)bh * Nn + i0) * Nn;

    if (tid < 64) {
        s_rth[tid] = g_rth[bh * Nn + i0 + tid];
        s_mx[tid]  = g_rmax[bh * Nn + i0 + tid];
    }
    __syncthreads();
    float rthr[2], mr[2], dloc[2];
#pragma unroll
    for (int i = 0; i < 2; i++) {
        rthr[i] = s_rth[2 * ty + i];
        mr[i]   = s_mx[2 * ty + i];
        dloc[i] = 0.f;
    }
    float acc[2][2][4] = {};                      // [mt][nt][frag]

    for (int j0 = 0; j0 < Nn; j0 += 32) {
        float4 araw[2];
#pragma unroll
        for (int i = 0; i < 2; i++)
            araw[i] = *(const float4*)&A[(size_t)(2 * ty + i) * Nn + j0 + 4 * tx];
        __syncthreads();                          // prev chunk MMA done
        if (tid < 32) s_cth[tid] = g_cth[bh * Nn + j0 + tid];
#pragma unroll
        for (int p = 0; p < 2; p++) {             // V chunk 32x64, split to Vs2
            int idx = p * 256 + tid;
            int jl = idx >> 4, d4 = (idx & 15) * 4;
            float4 v = *(const float4*)&V[(size_t)(j0 + jl) * HD + d4];
            Vs2[jl][d4 + 0] = split2_tf32(v.x);
            Vs2[jl][d4 + 1] = split2_tf32(v.y);
            Vs2[jl][d4 + 2] = split2_tf32(v.z);
            Vs2[jl][d4 + 3] = split2_tf32(v.w);
        }
        __syncthreads();                          // cth + Vs2 visible
#pragma unroll
        for (int i = 0; i < 2; i++) {             // exp + split P -> Ps2
            float av[4] = {araw[i].x, araw[i].y, araw[i].z, araw[i].w};
#pragma unroll
            for (int uu = 0; uu < 4; uu++) {
                float a = av[uu];
                float thr = fminf(rthr[i], s_cth[4 * tx + uu]);
                float p = (a >= thr) ? __expf(a - mr[i]) : 0.f;
                dloc[i] += p;
                Ps2[2 * ty + i][4 * tx + uu] = split2_tf32(p);
            }
        }
        __syncthreads();                          // Ps2 complete
#pragma unroll
        for (int ks = 0; ks < 4; ks++) {
            int k0 = ks * 8;
            unsigned ahi[2][4], alo[2][4], bhi[2][2], blo[2][2];
#pragma unroll
            for (int mt = 0; mt < 2; mt++) {
                int rb = 32 * wm + 16 * mt;
                uint2 q0 = Ps2[rb + g][k0 + t];
                uint2 q1 = Ps2[rb + g + 8][k0 + t];
                uint2 q2 = Ps2[rb + g][k0 + t + 4];
                uint2 q3 = Ps2[rb + g + 8][k0 + t + 4];
                ahi[mt][0] = q0.x; alo[mt][0] = q0.y;
                ahi[mt][1] = q1.x; alo[mt][1] = q1.y;
                ahi[mt][2] = q2.x; alo[mt][2] = q2.y;
                ahi[mt][3] = q3.x; alo[mt][3] = q3.y;
            }
#pragma unroll
            for (int nt = 0; nt < 2; nt++) {
                int nb = 16 * wn + 8 * nt;
                uint2 b0 = Vs2[k0 + t][nb + g];       // B[k][n] value = V[k][n]
                uint2 b1 = Vs2[k0 + t + 4][nb + g];
                bhi[nt][0] = b0.x; blo[nt][0] = b0.y;
                bhi[nt][1] = b1.x; blo[nt][1] = b1.y;
            }
#pragma unroll
            for (int mt = 0; mt < 2; mt++)
#pragma unroll
                for (int nt = 0; nt < 2; nt++) {
                    mma_tf32(acc[mt][nt], ahi[mt], blo[nt]);
                    mma_tf32(acc[mt][nt], alo[mt], bhi[nt]);
                    mma_tf32(acc[mt][nt], ahi[mt], bhi[nt]);
                }
        }
    }
    // deterministic denominator: 8 tx-lanes share row 2*ty+i
#pragma unroll
    for (int i = 0; i < 2; i++) {
        dloc[i] += __shfl_xor_sync(0xFFFFFFFFu, dloc[i], 1);
        dloc[i] += __shfl_xor_sync(0xFFFFFFFFu, dloc[i], 2);
        dloc[i] += __shfl_xor_sync(0xFFFFFFFFu, dloc[i], 4);
    }
    if (tx == 0) {
        s_den[2 * ty]     = dloc[0];
        s_den[2 * ty + 1] = dloc[1];
    }
    __syncthreads();
#pragma unroll
    for (int mt = 0; mt < 2; mt++) {
        int row0 = 32 * wm + 16 * mt + g;
        float inv0 = 1.f / s_den[row0];
        float inv1 = 1.f / s_den[row0 + 8];
#pragma unroll
        for (int nt = 0; nt < 2; nt++) {
            int col = 16 * wn + 8 * nt + 2 * t;
            float2 w0 = make_float2(acc[mt][nt][0] * inv0, acc[mt][nt][1] * inv0);
            float2 w1 = make_float2(acc[mt][nt][2] * inv1, acc[mt][nt][3] * inv1);
            *(float2*)&g_O[((size_t)bh * Nn + i0 + row0) * HD + col] = w0;
            *(float2*)&g_O[((size_t)bh * Nn + i0 + row0 + 8) * HD + col] = w1;
        }
    }
}

// ---------------------------------------------------------------------------
// Kernel 5: output projection   (R4 exact)
// ---------------------------------------------------------------------------
__global__ __launch_bounds__(128) void outproj_kernel(const float* __restrict__ Wp,
                                                      const float* __restrict__ bp,
                                                      float* __restrict__ out) {
    __shared__ float As[128][33];
    __shared__ float Bs[64][33];
    int tid = threadIdx.x;
    int tx = tid & 7, ty = tid >> 3;
    int m0 = blockIdx.y * 128, n0 = blockIdx.x * 64;
    float acc[8][8] = {};
    for (int k0 = 0; k0 < Cc; k0 += 32) {
        int h = k0 >> 6;
#pragma unroll
        for (int l = tid; l < 1024; l += 128) {
            int m = l >> 3, c = (l & 7) * 4;
            int mg = m0 + m;
            int bb = mg >> 11, nl = mg & (Nn - 1);
            int d = (k0 + c) & 63;
            float4 v = *(const float4*)&g_O[(((size_t)(bb * Hh + h)) * Nn + nl) * HD + d];
            As[m][c] = v.x; As[m][c + 1] = v.y; As[m][c + 2] = v.z; As[m][c + 3] = v.w;
        }
#pragma unroll
        for (int l = tid; l < 512; l += 128) {
            int n = l >> 3, c = (l & 7) * 4;
            float4 v = *(const float4*)&Wp[(size_t)(n0 + n) * Cc + k0 + c];
            Bs[n][c] = v.x; Bs[n][c + 1] = v.y; Bs[n][c + 2] = v.z; Bs[n][c + 3] = v.w;
        }
        __syncthreads();
#pragma unroll
        for (int kk = 0; kk < 32; kk++) {
            float a[8], b[8];
#pragma unroll
            for (int i = 0; i < 8; i++) a[i] = As[8 * ty + i][kk];
#pragma unroll
            for (int j = 0; j < 8; j++) b[j] = Bs[8 * tx + j][kk];
#pragma unroll
            for (int i = 0; i < 8; i++)
#pragma unroll
                for (int j = 0; j < 8; j++) acc[i][j] += a[i] * b[j];
        }
        __syncthreads();
    }
#pragma unroll
    for (int i = 0; i < 8; i++) {
        int m = m0 + 8 * ty + i;
#pragma unroll
        for (int j = 0; j < 8; j++) {
            int n = n0 + 8 * tx + j;
            out[(size_t)m * Cc + n] = acc[i][j] + bp[n];
        }
    }
}

// ---------------------------------------------------------------------------
extern "C" void kernel_launch(void* const* d_in, const int* in_sizes, int n_in,
                              void* d_out, int out_size) {
    (void)in_sizes; (void)n_in; (void)out_size;
    const float* q   = (const float*)d_in[0];
    const float* k_v = (const float*)d_in[1];
    const float* Wq  = (const float*)d_in[2];
    const float* Wk  = (const float*)d_in[3];
    const float* Wv  = (const float*)d_in[4];
    const float* Wp  = (const float*)d_in[5];
    const float* bp  = (const float*)d_in[6];
    float* out = (float*)d_out;

    dim3 gproj(Cc / 64, (Bb * Nn) / 128);              // (8, 32)
    proj_kernel<<<gproj, 128>>>(q,   Wq, 0);
    proj_kernel<<<gproj, 128>>>(k_v, Wk, 1);
    proj_kernel<<<gproj, 128>>>(k_v, Wv, 2);

    dim3 gqk(Nn / 32, Nn / 128, BH);                   // (64, 16, 16)
    qk_tc_kernel<<<gqk, 256>>>();

    dim3 gsel(BH * Nn, 2);
    select_kernel<<<gsel, 256>>>();

    dim3 gspv(Nn / 64, BH);                            // (32, 16)
    spv_tc_kernel<<<gspv, 256>>>();

    dim3 gout(Cc / 64, (Bb * Nn) / 128);
    outproj_kernel<<<gout, 128>>>(Wp, bp, out);
}

// round 10
// speedup vs baseline: 1.4477x; 1.0672x over previous
#include <cuda_runtime.h>
#include <cstdint>

#define Bb   2
#define Nn   2048
#define Cc   512
#define Hh   8
#define HD   64
#define BH   16
#define KTOP 1024
#define SCALEF 0.125f
#define JSPLIT 4
#define JLEN  (Nn / JSPLIT)     // 512

// ---------------- scratch ----------------
__device__ float g_Qh[BH * Nn * HD];
__device__ float g_Kh[BH * Nn * HD];
__device__ float g_Vh[BH * Nn * HD];
__device__ float g_attn[(size_t)BH * Nn * Nn];
__device__ float g_attnT[(size_t)BH * Nn * Nn];
__device__ float g_rth[BH * Nn];
__device__ float g_cth[BH * Nn];
__device__ float g_rmax[BH * Nn];
__device__ float g_O[BH * Nn * HD];
__device__ float g_Opart[(size_t)JSPLIT * BH * Nn * HD];   // 32MB
__device__ float g_dpart[JSPLIT * BH * Nn];

// ---------------- tf32 helpers ----------------
__device__ __forceinline__ unsigned tf32_rna(float x) {
    unsigned u; asm("cvt.rna.tf32.f32 %0, %1;" : "=r"(u) : "f"(x)); return u;
}
__device__ __forceinline__ void split_tf32(float x, unsigned& hi, unsigned& lo) {
    hi = tf32_rna(x);
    float hf = __uint_as_float(hi);
    lo = tf32_rna(x - hf);
}
__device__ __forceinline__ void mma_tf32(float* c, const unsigned* a, const unsigned* b) {
    asm("mma.sync.aligned.m16n8k8.row.col.f32.tf32.tf32.f32 "
        "{%0,%1,%2,%3},{%4,%5,%6,%7},{%8,%9},{%0,%1,%2,%3};"
        : "+f"(c[0]), "+f"(c[1]), "+f"(c[2]), "+f"(c[3])
        : "r"(a[0]), "r"(a[1]), "r"(a[2]), "r"(a[3]), "r"(b[0]), "r"(b[1]));
}

// ---------------------------------------------------------------------------
// Kernel 1: ALL THREE projections in one launch (grid.z = which).
// Core is R4-exact; only the X/W selection moved inside.
// ---------------------------------------------------------------------------
__global__ __launch_bounds__(128) void proj_kernel(const float* __restrict__ q,
                                                   const float* __restrict__ k_v,
                                                   const float* __restrict__ Wq,
                                                   const float* __restrict__ Wk,
                                                   const float* __restrict__ Wv) {
    __shared__ float As[128][33];
    __shared__ float Bs[64][33];
    int which = blockIdx.z;
    const float* X = (which == 0) ? q : k_v;
    const float* W = (which == 0) ? Wq : ((which == 1) ? Wk : Wv);
    int tid = threadIdx.x;
    int tx = tid & 7, ty = tid >> 3;
    int m0 = blockIdx.y * 128, n0 = blockIdx.x * 64;
    float acc[8][8] = {};
    for (int k0 = 0; k0 < Cc; k0 += 32) {
#pragma unroll
        for (int l = tid; l < 1024; l += 128) {
            int m = l >> 3, c = (l & 7) * 4;
            float4 v = *(const float4*)&X[(size_t)(m0 + m) * Cc + k0 + c];
            As[m][c] = v.x; As[m][c + 1] = v.y; As[m][c + 2] = v.z; As[m][c + 3] = v.w;
        }
#pragma unroll
        for (int l = tid; l < 512; l += 128) {
            int n = l >> 3, c = (l & 7) * 4;
            float4 v = *(const float4*)&W[(size_t)(n0 + n) * Cc + k0 + c];
            Bs[n][c] = v.x; Bs[n][c + 1] = v.y; Bs[n][c + 2] = v.z; Bs[n][c + 3] = v.w;
        }
        __syncthreads();
#pragma unroll
        for (int kk = 0; kk < 32; kk++) {
            float a[8], b[8];
#pragma unroll
            for (int i = 0; i < 8; i++) a[i] = As[8 * ty + i][kk];
#pragma unroll
            for (int j = 0; j < 8; j++) b[j] = Bs[8 * tx + j][kk];
#pragma unroll
            for (int i = 0; i < 8; i++)
#pragma unroll
                for (int j = 0; j < 8; j++) acc[i][j] += a[i] * b[j];
        }
        __syncthreads();
    }
    float* out = (which == 0) ? g_Qh : ((which == 1) ? g_Kh : g_Vh);
#pragma unroll
    for (int i = 0; i < 8; i++) {
        int m = m0 + 8 * ty + i;
        int bb = m >> 11, nl = m & (Nn - 1);
#pragma unroll
        for (int j = 0; j < 8; j++) {
            int n = n0 + 8 * tx + j;
            int h = n >> 6, d = n & 63;
            out[(((size_t)(bb * Hh + h)) * Nn + nl) * HD + d] = acc[i][j];
        }
    }
}

// ---------------------------------------------------------------------------
// Kernel 2: attn = scale * Q K^T via 3xTF32 mma.sync   (R4 exact)
// ---------------------------------------------------------------------------
__global__ __launch_bounds__(256) void qk_tc_kernel() {
    __shared__ float Qs[128][68];
    __shared__ float Ks[32][68];
    float (*Ts)[36] = (float(*)[36])Qs;

    int tid = threadIdx.x;
    int wid = tid >> 5, lane = tid & 31;
    int g = lane >> 2, t = lane & 3;
    int wm = wid & 3, wn = wid >> 2;
    int bh = blockIdx.z;
    int i0 = blockIdx.y * 128, j0 = blockIdx.x * 32;
    const float* Q = g_Qh + (size_t)bh * Nn * HD;
    const float* K = g_Kh + (size_t)bh * Nn * HD;

#pragma unroll
    for (int p = 0; p < 8; p++) {
        int idx = p * 256 + tid;
        int m = idx >> 4, c = (idx & 15) * 4;
        float4 v = *(const float4*)&Q[(size_t)(i0 + m) * HD + c];
        *(float4*)&Qs[m][c] = v;
    }
#pragma unroll
    for (int p = 0; p < 2; p++) {
        int idx = p * 256 + tid;
        int n = idx >> 4, c = (idx & 15) * 4;
        float4 v = *(const float4*)&K[(size_t)(j0 + n) * HD + c];
        *(float4*)&Ks[n][c] = v;
    }
    __syncthreads();

    float acc[2][2][4] = {};
#pragma unroll
    for (int ks = 0; ks < 8; ks++) {
        int k0 = ks * 8;
        unsigned ahi[2][4], alo[2][4], bhi[2][2], blo[2][2];
#pragma unroll
        for (int mt = 0; mt < 2; mt++) {
            int rb = 32 * wm + 16 * mt;
            float x0 = Qs[rb + g][k0 + t];
            float x1 = Qs[rb + g + 8][k0 + t];
            float x2 = Qs[rb + g][k0 + t + 4];
            float x3 = Qs[rb + g + 8][k0 + t + 4];
            split_tf32(x0, ahi[mt][0], alo[mt][0]);
            split_tf32(x1, ahi[mt][1], alo[mt][1]);
            split_tf32(x2, ahi[mt][2], alo[mt][2]);
            split_tf32(x3, ahi[mt][3], alo[mt][3]);
        }
#pragma unroll
        for (int nt = 0; nt < 2; nt++) {
            int nb = 16 * wn + 8 * nt;
            float y0 = Ks[nb + g][k0 + t];
            float y1 = Ks[nb + g][k0 + t + 4];
            split_tf32(y0, bhi[nt][0], blo[nt][0]);
            split_tf32(y1, bhi[nt][1], blo[nt][1]);
        }
#pragma unroll
        for (int mt = 0; mt < 2; mt++)
#pragma unroll
            for (int nt = 0; nt < 2; nt++) {
                mma_tf32(acc[mt][nt], ahi[mt], blo[nt]);
                mma_tf32(acc[mt][nt], alo[mt], bhi[nt]);
                mma_tf32(acc[mt][nt], ahi[mt], bhi[nt]);
            }
    }
    __syncthreads();

#pragma unroll
    for (int mt = 0; mt < 2; mt++)
#pragma unroll
        for (int nt = 0; nt < 2; nt++) {
            int r0 = 32 * wm + 16 * mt + g;
            int c0 = 16 * wn + 8 * nt + 2 * t;
            Ts[r0][c0]         = acc[mt][nt][0] * SCALEF;
            Ts[r0][c0 + 1]     = acc[mt][nt][1] * SCALEF;
            Ts[r0 + 8][c0]     = acc[mt][nt][2] * SCALEF;
            Ts[r0 + 8][c0 + 1] = acc[mt][nt][3] * SCALEF;
        }
    __syncthreads();

    float* attn = g_attn + ((size_t)bh * Nn + i0) * Nn + j0;
#pragma unroll
    for (int p = 0; p < 4; p++) {
        int idx = p * 256 + tid;
        int r = idx >> 3, cq = (idx & 7) * 4;
        *(float4*)&attn[(size_t)r * Nn + cq] = *(const float4*)&Ts[r][cq];
    }
    float* attnT = g_attnT + ((size_t)bh * Nn + j0) * Nn + i0;
#pragma unroll
    for (int p = 0; p < 16; p++) {
        int idx = p * 256 + tid;
        int jl = idx >> 7, il = idx & 127;
        attnT[(size_t)jl * Nn + il] = Ts[il][jl];
    }
}

// ---------------------------------------------------------------------------
// Kernel 3: exact K_TOP-th largest per row (radix select)   (R4 exact)
// ---------------------------------------------------------------------------
__global__ __launch_bounds__(256) void select_kernel() {
    __shared__ unsigned hist[4][256];
    __shared__ unsigned S[257];
    __shared__ unsigned s_sel, s_maxu;
    int tid = threadIdx.x;
    size_t row = blockIdx.x;
    int dir = blockIdx.y;
    const float* src = (dir ? g_attnT : g_attn) + row * Nn;

    unsigned u[8], lmax = 0u;
#pragma unroll
    for (int r = 0; r < 8; r++) {
        unsigned b = __float_as_uint(src[tid + 256 * r]);
        u[r] = b ^ ((unsigned)((int)b >> 31) | 0x80000000u);
        lmax = lmax > u[r] ? lmax : u[r];
    }
    if (tid == 0) s_maxu = 0u;

    unsigned prefix = 0u;
    int krem = KTOP;
    int hb = tid >> 6;
#pragma unroll
    for (int pass = 0; pass < 4; pass++) {
        int shift = 24 - 8 * pass;
        hist[0][tid] = 0u; hist[1][tid] = 0u; hist[2][tid] = 0u; hist[3][tid] = 0u;
        __syncthreads();
        if (pass == 0) atomicMax(&s_maxu, lmax);
        unsigned himask = (pass == 0) ? 0u : (0xFFFFFFFFu << (shift + 8));
#pragma unroll
        for (int r = 0; r < 8; r++)
            if ((u[r] & himask) == prefix)
                atomicAdd(&hist[hb][(u[r] >> shift) & 255u], 1u);
        __syncthreads();
        unsigned h = hist[0][tid] + hist[1][tid] + hist[2][tid] + hist[3][tid];
        hist[0][tid] = h;
        __syncthreads();
        if (tid < 32) {
            int base = tid * 8;
            unsigned c[8], loc[8];
#pragma unroll
            for (int j = 0; j < 8; j++) c[j] = hist[0][base + j];
            loc[7] = c[7];
#pragma unroll
            for (int j = 6; j >= 0; j--) loc[j] = c[j] + loc[j + 1];
            unsigned T = loc[0], incl = T;
#pragma unroll
            for (int off = 1; off < 32; off <<= 1) {
                unsigned v = __shfl_down_sync(0xFFFFFFFFu, incl, off);
                if (tid + off < 32) incl += v;
            }
            unsigned excl = incl - T;
#pragma unroll
            for (int j = 0; j < 8; j++) S[base + j] = excl + loc[j];
            if (tid == 0) S[256] = 0u;
        }
        __syncthreads();
        unsigned St = S[tid], St1 = S[tid + 1];
        if ((int)St >= krem && (int)St1 < krem) s_sel = (unsigned)tid;
        __syncthreads();
        unsigned sel = s_sel;
        krem -= (int)S[sel + 1];
        prefix |= sel << shift;
        __syncthreads();
    }
    if (tid == 0) {
        unsigned b = (prefix & 0x80000000u) ? (prefix ^ 0x80000000u) : ~prefix;
        float thr = __uint_as_float(b);
        if (dir) {
            g_cth[row] = thr;
        } else {
            g_rth[row] = thr;
            unsigned um = s_maxu;
            unsigned bm = (um & 0x80000000u) ? (um ^ 0x80000000u) : ~um;
            g_rmax[row] = __uint_as_float(bm);
        }
    }
}

// ---------------------------------------------------------------------------
// Kernel 4: fused masked softmax + P@V, J-SPLIT partials.
// R4 spv core exactly, but each block covers a 512-token j-range
// (part = blockIdx.y) and writes UNNORMALIZED partial O + partial denom.
// grid (Nn/128, JSPLIT, BH), block 128.
// ---------------------------------------------------------------------------
__global__ __launch_bounds__(128) void spv_part_kernel() {
    __shared__ float Ps[128][33];
    __shared__ float Vs[32][68];
    __shared__ float s_rth[128], s_mx[128], s_cth[32], s_den[128];
    int tid = threadIdx.x;
    int tx = tid & 7, ty = tid >> 3;
    int bh = blockIdx.z;
    int part = blockIdx.y;
    int js = part * JLEN;
    int i0 = blockIdx.x * 128;
    const float* V = g_Vh + (size_t)bh * Nn * HD;
    const float* A = g_attn + ((size_t)bh * Nn + i0) * Nn;
    s_rth[tid] = g_rth[bh * Nn + i0 + tid];
    s_mx[tid]  = g_rmax[bh * Nn + i0 + tid];
    s_den[tid] = 0.f;
    __syncthreads();
    float rthr[8], mr[8], dloc[8];
#pragma unroll
    for (int i = 0; i < 8; i++) {
        rthr[i] = s_rth[8 * ty + i];
        mr[i]   = s_mx[8 * ty + i];
        dloc[i] = 0.f;
    }
    float acc[8][8] = {};

    for (int j0 = js; j0 < js + JLEN; j0 += 32) {
        float4 araw[8];
#pragma unroll
        for (int i = 0; i < 8; i++)
            araw[i] = *(const float4*)&A[(size_t)(8 * ty + i) * Nn + j0 + 4 * tx];
        __syncthreads();
        if (tid < 32) s_cth[tid] = g_cth[bh * Nn + j0 + tid];
#pragma unroll
        for (int l = tid; l < 512; l += 128) {
            int jl = l >> 4, d = (l & 15) * 4;
            *(float4*)&Vs[jl][d] = *(const float4*)&V[(size_t)(j0 + jl) * HD + d];
        }
        __syncthreads();
#pragma unroll
        for (int i = 0; i < 8; i++) {
            float av[4] = {araw[i].x, araw[i].y, araw[i].z, araw[i].w};
#pragma unroll
            for (int uu = 0; uu < 4; uu++) {
                float a = av[uu];
                float thr = fminf(rthr[i], s_cth[4 * tx + uu]);
                float p = (a >= thr) ? __expf(a - mr[i]) : 0.f;
                dloc[i] += p;
                Ps[8 * ty + i][4 * tx + uu] = p;
            }
        }
        __syncthreads();
#pragma unroll
        for (int kk = 0; kk < 32; kk++) {
            float a[8], b[8];
#pragma unroll
            for (int i = 0; i < 8; i++) a[i] = Ps[8 * ty + i][kk];
            float4 b0 = *(const float4*)&Vs[kk][8 * tx];
            float4 b1 = *(const float4*)&Vs[kk][8 * tx + 4];
            b[0] = b0.x; b[1] = b0.y; b[2] = b0.z; b[3] = b0.w;
            b[4] = b1.x; b[5] = b1.y; b[6] = b1.z; b[7] = b1.w;
#pragma unroll
            for (int i = 0; i < 8; i++)
#pragma unroll
                for (int j = 0; j < 8; j++) acc[i][j] += a[i] * b[j];
        }
    }
#pragma unroll
    for (int i = 0; i < 8; i++) atomicAdd(&s_den[8 * ty + i], dloc[i]);
    __syncthreads();
    // partial denom: one thread per row
    {
        size_t rowg = (size_t)bh * Nn + i0 + tid;
        g_dpart[(size_t)part * BH * Nn + rowg] = s_den[tid];
    }
    float* Op = g_Opart + (size_t)part * BH * Nn * HD;
#pragma unroll
    for (int i = 0; i < 8; i++) {
        int il = 8 * ty + i;
        float4 v0 = make_float4(acc[i][0], acc[i][1], acc[i][2], acc[i][3]);
        float4 v1 = make_float4(acc[i][4], acc[i][5], acc[i][6], acc[i][7]);
        float* o = &Op[((size_t)bh * Nn + i0 + il) * HD + 8 * tx];
        *(float4*)o = v0;
        *(float4*)(o + 4) = v1;
    }
}

// ---------------------------------------------------------------------------
// Kernel 4b: merge partials -> g_O.  2048 blocks x 256 thr, float4/thread.
// ---------------------------------------------------------------------------
__global__ __launch_bounds__(256) void spv_merge_kernel() {
    int gid = blockIdx.x * 256 + threadIdx.x;      // 0 .. BH*Nn*HD/4-1
    size_t row = (size_t)gid >> 4;                 // BH*Nn rows, HD/4=16 quads
    int dd = (gid & 15) * 4;
    float den = g_dpart[row] + g_dpart[BH * Nn + row]
              + g_dpart[2 * BH * Nn + row] + g_dpart[3 * BH * Nn + row];
    float inv = 1.f / den;
    size_t base = row * HD + dd;
    float4 s0 = *(const float4*)&g_Opart[base];
    float4 s1 = *(const float4*)&g_Opart[(size_t)BH * Nn * HD + base];
    float4 s2 = *(const float4*)&g_Opart[2 * (size_t)BH * Nn * HD + base];
    float4 s3 = *(const float4*)&g_Opart[3 * (size_t)BH * Nn * HD + base];
    float4 r;
    r.x = (s0.x + s1.x + s2.x + s3.x) * inv;
    r.y = (s0.y + s1.y + s2.y + s3.y) * inv;
    r.z = (s0.z + s1.z + s2.z + s3.z) * inv;
    r.w = (s0.w + s1.w + s2.w + s3.w) * inv;
    *(float4*)&g_O[base] = r;
}

// ---------------------------------------------------------------------------
// Kernel 5: output projection   (R4 exact)
// ---------------------------------------------------------------------------
__global__ __launch_bounds__(128) void outproj_kernel(const float* __restrict__ Wp,
                                                      const float* __restrict__ bp,
                                                      float* __restrict__ out) {
    __shared__ float As[128][33];
    __shared__ float Bs[64][33];
    int tid = threadIdx.x;
    int tx = tid & 7, ty = tid >> 3;
    int m0 = blockIdx.y * 128, n0 = blockIdx.x * 64;
    float acc[8][8] = {};
    for (int k0 = 0; k0 < Cc; k0 += 32) {
        int h = k0 >> 6;
#pragma unroll
        for (int l = tid; l < 1024; l += 128) {
            int m = l >> 3, c = (l & 7) * 4;
            int mg = m0 + m;
            int bb = mg >> 11, nl = mg & (Nn - 1);
            int d = (k0 + c) & 63;
            float4 v = *(const float4*)&g_O[(((size_t)(bb * Hh + h)) * Nn + nl) * HD + d];
            As[m][c] = v.x; As[m][c + 1] = v.y; As[m][c + 2] = v.z; As[m][c + 3] = v.w;
        }
#pragma unroll
        for (int l = tid; l < 512; l += 128) {
            int n = l >> 3, c = (l & 7) * 4;
            float4 v = *(const float4*)&Wp[(size_t)(n0 + n) * Cc + k0 + c];
            Bs[n][c] = v.x; Bs[n][c + 1] = v.y; Bs[n][c + 2] = v.z; Bs[n][c + 3] = v.w;
        }
        __syncthreads();
#pragma unroll
        for (int kk = 0; kk < 32; kk++) {
            float a[8], b[8];
#pragma unroll
            for (int i = 0; i < 8; i++) a[i] = As[8 * ty + i][kk];
#pragma unroll
            for (int j = 0; j < 8; j++) b[j] = Bs[8 * tx + j][kk];
#pragma unroll
            for (int i = 0; i < 8; i++)
#pragma unroll
                for (int j = 0; j < 8; j++) acc[i][j] += a[i] * b[j];
        }
        __syncthreads();
    }
#pragma unroll
    for (int i = 0; i < 8; i++) {
        int m = m0 + 8 * ty + i;
#pragma unroll
        for (int j = 0; j < 8; j++) {
            int n = n0 + 8 * tx + j;
            out[(size_t)m * Cc + n] = acc[i][j] + bp[n];
        }
    }
}

// ---------------------------------------------------------------------------
extern "C" void kernel_launch(void* const* d_in, const int* in_sizes, int n_in,
                              void* d_out, int out_size) {
    (void)in_sizes; (void)n_in; (void)out_size;
    const float* q   = (const float*)d_in[0];
    const float* k_v = (const float*)d_in[1];
    const float* Wq  = (const float*)d_in[2];
    const float* Wk  = (const float*)d_in[3];
    const float* Wv  = (const float*)d_in[4];
    const float* Wp  = (const float*)d_in[5];
    const float* bp  = (const float*)d_in[6];
    float* out = (float*)d_out;

    dim3 gproj(Cc / 64, (Bb * Nn) / 128, 3);           // (8, 32, 3): one launch
    proj_kernel<<<gproj, 128>>>(q, k_v, Wq, Wk, Wv);

    dim3 gqk(Nn / 32, Nn / 128, BH);                   // (64, 16, 16)
    qk_tc_kernel<<<gqk, 256>>>();

    dim3 gsel(BH * Nn, 2);
    select_kernel<<<gsel, 256>>>();

    dim3 gspv(Nn / 128, JSPLIT, BH);                   // (16, 4, 16) = 1024 blocks
    spv_part_kernel<<<gspv, 128>>>();

    spv_merge_kernel<<<(BH * Nn * HD / 4) / 256, 256>>>();

    dim3 gout(Cc / 64, (Bb * Nn) / 128);
    outproj_kernel<<<gout, 128>>>(Wp, bp, out);
}